// round 4
// baseline (speedup 1.0000x reference)
#include <cuda_runtime.h>
#include <math.h>

#define T_ 262144
#define K_ 32
#define D_ 64
#define CHUNKS 2048
#define CLEN 128
#define L2E 1.4426950408889634f
#define LN2 0.6931471805599453f

// ---------------- device scratch (static globals: no allocations allowed) ----------------
__device__ __align__(16) float g_Aexp[K_ * K_];    // softmax(A) rows (linear domain)
__device__ __align__(16) float g_logA2[K_ * K_];   // log2-softmax(A)
__device__ __align__(16) float g_pi02[K_];         // log2-softmax(pi)
__device__ __align__(16) float g_kc[K_];           // per-state constant (natural log)
__device__ __align__(16) float g_am1[K_];          // a - 1
__device__ __align__(16) float g_bb[K_];           // rate b
__device__ __align__(16) float g_muiv[K_ * D_];    // mu * inv_var
__device__ __align__(16) float g_ivh[K_ * D_];     // -0.5 * inv_var
__device__ __align__(16) float g_ll2[(size_t)T_ * K_];          // per-step log2-likelihood [T,32]
__device__ __align__(16) float g_M[2][(size_t)CHUNKS * K_ * K_]; // chunk matrices, ping-pong

// ---------------- K0: tiny setup (1 block, 1024 threads) ----------------
__global__ void k0_setup(const float* __restrict__ A, const float* __restrict__ log_ab,
                         const float* __restrict__ mu, const float* __restrict__ log_sigma,
                         const float* __restrict__ pi)
{
    int tid = threadIdx.x;
    int i = tid >> 5, j = tid & 31;

    // row-softmax of A (warp i handles row i, lanes = j)
    float a = A[i * 32 + j];
    float m = a;
#pragma unroll
    for (int o = 16; o; o >>= 1) m = fmaxf(m, __shfl_xor_sync(0xffffffffu, m, o));
    float t2 = (a - m) * L2E;
    float e = exp2f(t2);
    float s = e;
#pragma unroll
    for (int o = 16; o; o >>= 1) s += __shfl_xor_sync(0xffffffffu, s, o);
    float lg = __log2f(s);
    g_Aexp[i * 32 + j] = e / s;
    g_logA2[i * 32 + j] = t2 - lg;

    if (i == 0) {  // log2-softmax(pi)
        float p = pi[j];
        float pm = p;
#pragma unroll
        for (int o = 16; o; o >>= 1) pm = fmaxf(pm, __shfl_xor_sync(0xffffffffu, pm, o));
        float pe = exp2f((p - pm) * L2E);
        float ps = pe;
#pragma unroll
        for (int o = 16; o; o >>= 1) ps += __shfl_xor_sync(0xffffffffu, ps, o);
        g_pi02[j] = (p - pm) * L2E - __log2f(ps);
    }
    if (i == 1) {  // per-state gamma + gaussian constants (thread j = state k)
        int k = j;
        float la = log_ab[k * 2 + 0], lb = log_ab[k * 2 + 1];
        float av = expf(la), bv = expf(lb);
        float cg = av * lb - lgammaf(av);
        float sls = 0.f, smm = 0.f;
        for (int d = 0; d < D_; d++) {
            float ls = log_sigma[k * D_ + d];
            float iv = expf(-2.f * ls);
            float mm = mu[k * D_ + d];
            g_muiv[k * D_ + d] = mm * iv;
            g_ivh[k * D_ + d] = -0.5f * iv;
            sls += ls;
            smm += mm * mm * iv;
        }
        g_kc[k] = cg - sls - 0.5f * smm - 0.5f * (float)D_ * logf(6.283185307179586f);
        g_am1[k] = av - 1.f;
        g_bb[k] = bv;
    }
}

// ---------------- K1: ll2[T,32] + h copy (GEMM-style tiling) ----------------
__global__ void __launch_bounds__(128) k1_ll(const float* __restrict__ Y,
                                             const float* __restrict__ dT,
                                             float* __restrict__ hout)
{
    __shared__ float sY[64 * 65];
    __shared__ float sM[32 * 65];
    __shared__ float sH[32 * 65];
    __shared__ float skc[32], sam1[32], sb[32];
    int tid = threadIdx.x;
    size_t t0 = (size_t)blockIdx.x * 64;

    const float4* Y4 = reinterpret_cast<const float4*>(Y);
    float4* h4 = reinterpret_cast<float4*>(hout);
#pragma unroll
    for (int it = 0; it < 8; it++) {  // stage Y tile + emit h
        int f = tid + it * 128;
        float4 v = Y4[t0 * 16 + f];
        h4[t0 * 16 + f] = v;
        int row = f >> 4;
        int col = (f & 15) << 2;
        sY[row * 65 + col + 0] = v.x; sY[row * 65 + col + 1] = v.y;
        sY[row * 65 + col + 2] = v.z; sY[row * 65 + col + 3] = v.w;
    }
#pragma unroll
    for (int it = 0; it < 16; it++) {  // stage params
        int e = tid + it * 128;
        int k = e >> 6, d = e & 63;
        sM[k * 65 + d] = g_muiv[e];
        sH[k * 65 + d] = g_ivh[e];
    }
    if (tid < 32) { skc[tid] = g_kc[tid]; sam1[tid] = g_am1[tid]; sb[tid] = g_bb[tid]; }
    __syncthreads();

    int kq = tid & 7, tg = tid >> 3;   // 8 k-groups x 16 t-groups
    int k4 = kq * 4, t4 = tg * 4;
    float acc[4][4];
#pragma unroll
    for (int a = 0; a < 4; a++)
#pragma unroll
        for (int b = 0; b < 4; b++) acc[a][b] = 0.f;

#pragma unroll 4
    for (int d = 0; d < 64; d++) {
        float yv[4];
#pragma unroll
        for (int tt = 0; tt < 4; tt++) yv[tt] = sY[(t4 + tt) * 65 + d];
#pragma unroll
        for (int kk = 0; kk < 4; kk++) {
            float mv = sM[(k4 + kk) * 65 + d];
            float hv = sH[(k4 + kk) * 65 + d];
#pragma unroll
            for (int tt = 0; tt < 4; tt++)
                acc[tt][kk] = fmaf(yv[tt], fmaf(hv, yv[tt], mv), acc[tt][kk]);
        }
    }

    float4* ll2v = reinterpret_cast<float4*>(g_ll2);
#pragma unroll
    for (int tt = 0; tt < 4; tt++) {
        size_t t = t0 + t4 + tt;
        float dt = dT[t];
        float ldt = logf(dt);
        float4 o;
        float* op = &o.x;
#pragma unroll
        for (int kk = 0; kk < 4; kk++) {
            int k = k4 + kk;
            float ll = acc[tt][kk] + skc[k] + sam1[k] * ldt - dt * sb[k];
            op[kk] = ll * L2E;
        }
        ll2v[t * 8 + kq] = o;
    }
}

// ---------------- K2: chunk scan (one 32x32 log-transition matrix per chunk) ----------------
// Per step: P = E @ softmax(A) in linear domain with per-row offsets; E row-renormalized.
__global__ void __launch_bounds__(64) k2_scan()
{
    __shared__ __align__(16) float sE[2][32 * 36];  // E^T double buffer [m][i]
    __shared__ __align__(16) float sA[32 * 36];     // Aexp [m][j]
    int tid = threadIdx.x;
    int c = blockIdx.x;
    int tc = tid & 7, tr = tid >> 3;    // 8 j-cols x 8 i-rows of 4x4 tiles
    int j0 = tc * 4, i0 = tr * 4;

#pragma unroll
    for (int it = 0; it < 16; it++) {
        int e = tid + it * 64;
        sA[(e >> 5) * 36 + (e & 31)] = g_Aexp[e];
    }
    int s = 1 + c * CLEN;
    int e_ = min(T_, s + CLEN);
    const float4* ll2v = reinterpret_cast<const float4*>(g_ll2);

    float vrel[4][4], O[4];
    {   // init M = logA2 + ll2[s]
        float4 llv = ll2v[(size_t)s * 8 + tc];
        float llj[4] = {llv.x, llv.y, llv.z, llv.w};
#pragma unroll
        for (int ii = 0; ii < 4; ii++) {
            float4 la = reinterpret_cast<const float4*>(g_logA2)[(i0 + ii) * 8 + tc];
            float v0 = la.x + llj[0], v1 = la.y + llj[1], v2 = la.z + llj[2], v3 = la.w + llj[3];
            float vm = fmaxf(fmaxf(v0, v1), fmaxf(v2, v3));
#pragma unroll
            for (int o = 1; o < 8; o <<= 1) vm = fmaxf(vm, __shfl_xor_sync(0xffffffffu, vm, o));
            O[ii] = vm;
            vrel[ii][0] = v0 - vm; vrel[ii][1] = v1 - vm;
            vrel[ii][2] = v2 - vm; vrel[ii][3] = v3 - vm;
        }
#pragma unroll
        for (int jj = 0; jj < 4; jj++) {
            float4 w;
            w.x = exp2f(vrel[0][jj]); w.y = exp2f(vrel[1][jj]);
            w.z = exp2f(vrel[2][jj]); w.w = exp2f(vrel[3][jj]);
            *reinterpret_cast<float4*>(&sE[0][(j0 + jj) * 36 + i0]) = w;
        }
    }
    float4 lln = make_float4(0.f, 0.f, 0.f, 0.f);
    if (s + 1 < e_) lln = ll2v[(size_t)(s + 1) * 8 + tc];
    __syncthreads();

    int p = 0;
    for (int t = s + 1; t < e_; t++) {
        float llc0 = lln.x, llc1 = lln.y, llc2 = lln.z, llc3 = lln.w;
        if (t + 1 < e_) lln = ll2v[(size_t)(t + 1) * 8 + tc];
        float acc[4][4];
#pragma unroll
        for (int a = 0; a < 4; a++)
#pragma unroll
            for (int b = 0; b < 4; b++) acc[a][b] = 0.f;
#pragma unroll
        for (int m = 0; m < 32; m++) {
            float4 a4 = *reinterpret_cast<const float4*>(&sE[p][m * 36 + i0]);
            float4 b4 = *reinterpret_cast<const float4*>(&sA[m * 36 + j0]);
            acc[0][0] = fmaf(a4.x, b4.x, acc[0][0]); acc[0][1] = fmaf(a4.x, b4.y, acc[0][1]);
            acc[0][2] = fmaf(a4.x, b4.z, acc[0][2]); acc[0][3] = fmaf(a4.x, b4.w, acc[0][3]);
            acc[1][0] = fmaf(a4.y, b4.x, acc[1][0]); acc[1][1] = fmaf(a4.y, b4.y, acc[1][1]);
            acc[1][2] = fmaf(a4.y, b4.z, acc[1][2]); acc[1][3] = fmaf(a4.y, b4.w, acc[1][3]);
            acc[2][0] = fmaf(a4.z, b4.x, acc[2][0]); acc[2][1] = fmaf(a4.z, b4.y, acc[2][1]);
            acc[2][2] = fmaf(a4.z, b4.z, acc[2][2]); acc[2][3] = fmaf(a4.z, b4.w, acc[2][3]);
            acc[3][0] = fmaf(a4.w, b4.x, acc[3][0]); acc[3][1] = fmaf(a4.w, b4.y, acc[3][1]);
            acc[3][2] = fmaf(a4.w, b4.z, acc[3][2]); acc[3][3] = fmaf(a4.w, b4.w, acc[3][3]);
        }
#pragma unroll
        for (int ii = 0; ii < 4; ii++) {
            float v0 = __log2f(acc[ii][0]) + llc0;
            float v1 = __log2f(acc[ii][1]) + llc1;
            float v2 = __log2f(acc[ii][2]) + llc2;
            float v3 = __log2f(acc[ii][3]) + llc3;
            float vm = fmaxf(fmaxf(v0, v1), fmaxf(v2, v3));
#pragma unroll
            for (int o = 1; o < 8; o <<= 1) vm = fmaxf(vm, __shfl_xor_sync(0xffffffffu, vm, o));
            O[ii] += vm;
            vrel[ii][0] = v0 - vm; vrel[ii][1] = v1 - vm;
            vrel[ii][2] = v2 - vm; vrel[ii][3] = v3 - vm;
        }
        int q = p ^ 1;
#pragma unroll
        for (int jj = 0; jj < 4; jj++) {
            float4 w;
            w.x = exp2f(vrel[0][jj]); w.y = exp2f(vrel[1][jj]);
            w.z = exp2f(vrel[2][jj]); w.w = exp2f(vrel[3][jj]);
            *reinterpret_cast<float4*>(&sE[q][(j0 + jj) * 36 + i0]) = w;
        }
        __syncthreads();
        p = q;
    }
    // emit chunk matrix (log2 domain)
#pragma unroll
    for (int ii = 0; ii < 4; ii++) {
        float4 o;
        o.x = O[ii] + vrel[ii][0]; o.y = O[ii] + vrel[ii][1];
        o.z = O[ii] + vrel[ii][2]; o.w = O[ii] + vrel[ii][3];
        reinterpret_cast<float4*>(g_M[0])[(size_t)c * 256 + (i0 + ii) * 8 + tc] = o;
    }
}

// ---------------- K3: order-preserving pairwise log-matmul tree reduce ----------------
__global__ void __launch_bounds__(1024, 1) k3_combine(int srcSel)
{
    const float* __restrict__ src = g_M[srcSel];
    float* __restrict__ dst = g_M[srcSel ^ 1];
    __shared__ float sMa[32 * 33];
    __shared__ float sMb[32 * 33];
    int tid = threadIdx.x;
    int i = tid >> 5, j = tid & 31;
    size_t base = (size_t)blockIdx.x * 2048;
    sMa[i * 33 + j] = src[base + i * 32 + j];
    sMb[i * 33 + j] = src[base + 1024 + i * 32 + j];
    __syncthreads();
    float v[32];
    float vm = -3.0e38f;
#pragma unroll
    for (int m = 0; m < 32; m++) {
        v[m] = sMa[i * 33 + m] + sMb[m * 33 + j];
        vm = fmaxf(vm, v[m]);
    }
    float s = 0.f;
#pragma unroll
    for (int m = 0; m < 32; m++) s += exp2f(v[m] - vm);
    dst[(size_t)blockIdx.x * 1024 + i * 32 + j] = vm + __log2f(s);
}

// ---------------- K4: contract alpha0 with final matrix -> loss scalar ----------------
__global__ void k4_final(float* __restrict__ out, int outIdx, int sel)
{
    __shared__ float red[32];
    __shared__ float bval;
    int tid = threadIdx.x;
    int i = tid >> 5, j = tid & 31;
    float v = g_pi02[i] + g_ll2[i] + g_M[sel][i * 32 + j];  // g_ll2[0*32+i]
    float m = v;
#pragma unroll
    for (int o = 16; o; o >>= 1) m = fmaxf(m, __shfl_xor_sync(0xffffffffu, m, o));
    if (j == 0) red[i] = m;
    __syncthreads();
    if (tid < 32) {
        float t = red[tid];
#pragma unroll
        for (int o = 16; o; o >>= 1) t = fmaxf(t, __shfl_xor_sync(0xffffffffu, t, o));
        if (tid == 0) bval = t;
    }
    __syncthreads();
    float bmax = bval;
    float e = exp2f(v - bmax);
#pragma unroll
    for (int o = 16; o; o >>= 1) e += __shfl_xor_sync(0xffffffffu, e, o);
    __syncthreads();
    if (j == 0) red[i] = e;
    __syncthreads();
    if (tid < 32) {
        float t = red[tid];
#pragma unroll
        for (int o = 16; o; o >>= 1) t += __shfl_xor_sync(0xffffffffu, t, o);
        if (tid == 0) out[outIdx] = -((bmax + __log2f(t)) * LN2);
    }
}

// ---------------- launch ----------------
extern "C" void kernel_launch(void* const* d_in, const int* in_sizes, int n_in,
                              void* d_out, int out_size)
{
    const float* Y = (const float*)d_in[0];
    const float* dT = (const float*)d_in[1];
    const float* A = (const float*)d_in[2];
    const float* log_ab = (const float*)d_in[3];
    const float* mu = (const float*)d_in[4];
    const float* log_sigma = (const float*)d_in[5];
    const float* pi = (const float*)d_in[6];
    float* out = (float*)d_out;

    k0_setup<<<1, 1024>>>(A, log_ab, mu, log_sigma, pi);
    k1_ll<<<T_ / 64, 128>>>(Y, dT, out);
    k2_scan<<<CHUNKS, 64>>>();
    int P = CHUNKS, sel = 0;
    while (P > 1) {
        k3_combine<<<P / 2, 1024>>>(sel);
        sel ^= 1;
        P >>= 1;
    }
    k4_final<<<1, 1024>>>(out, out_size - 1, sel);
}

// round 6
// speedup vs baseline: 1.0077x; 1.0077x over previous
#include <cuda_runtime.h>
#include <math.h>

#define T_ 262144
#define K_ 32
#define D_ 64
#define CHUNKS 2048
#define CLEN 128
#define L2E 1.4426950408889634f
#define LN2 0.6931471805599453f

typedef unsigned long long ull;
union U4 { float4 v; ull u[2]; };

// ---------------- packed f32x2 helpers (sm_103a) ----------------
#define FMA2(d, a, b) asm("fma.rn.f32x2 %0, %1, %2, %0;" : "+l"(d) : "l"(a), "l"(b))
#define MUL2(d, b)    asm("mul.rn.f32x2 %0, %0, %1;"     : "+l"(d) : "l"(b))
__device__ __forceinline__ ull dup2(float x) {
    ull r; unsigned u = __float_as_uint(x);
    asm("mov.b64 %0, {%1, %1};" : "=l"(r) : "r"(u));
    return r;
}
__device__ __forceinline__ float2 uf(ull x) {
    float2 f;
    asm("mov.b64 {%0, %1}, %2;" : "=f"(f.x), "=f"(f.y) : "l"(x));
    return f;
}
__device__ __forceinline__ ull add2(ull a, ull b) {
    ull d; asm("add.rn.f32x2 %0, %1, %2;" : "=l"(d) : "l"(a), "l"(b)); return d;
}
__device__ __forceinline__ float fexp2(float x) { float r; asm("ex2.approx.f32 %0, %1;" : "=f"(r) : "f"(x)); return r; }
__device__ __forceinline__ float flog2(float x) { float r; asm("lg2.approx.f32 %0, %1;" : "=f"(r) : "f"(x)); return r; }
__device__ __forceinline__ float frcp(float x)  { float r; asm("rcp.approx.f32 %0, %1;" : "=f"(r) : "f"(x)); return r; }

// ---------------- device scratch ----------------
__device__ __align__(16) float g_Aexp[K_ * K_];    // softmax(A) rows (linear)
__device__ __align__(16) float g_pi02[K_];         // log2-softmax(pi)
__device__ __align__(16) float g_ll0[K_];          // ll (log2) at t=0
__device__ __align__(16) float g_kc[K_];           // per-state const (natural log)
__device__ __align__(16) float g_am1[K_];          // a - 1
__device__ __align__(16) float g_bb[K_];           // rate b
__device__ __align__(16) float g_muiv[K_ * D_];    // mu * inv_var
__device__ __align__(16) float g_ivh[K_ * D_];     // -0.5 * inv_var
__device__ __align__(16) float g_w[(size_t)T_ * K_];   // exp2(ll2 - c_t), linear weights
__device__ __align__(16) float g_c[T_];                // per-t max of ll2
__device__ __align__(16) float g_M[2][(size_t)CHUNKS * K_ * K_]; // chunk matrices (log2), ping-pong

// ---------------- K0: setup ----------------
__global__ void k0_setup(const float* __restrict__ A, const float* __restrict__ log_ab,
                         const float* __restrict__ mu, const float* __restrict__ log_sigma,
                         const float* __restrict__ pi)
{
    int tid = threadIdx.x;
    int i = tid >> 5, j = tid & 31;

    float a = A[i * 32 + j];
    float m = a;
#pragma unroll
    for (int o = 16; o; o >>= 1) m = fmaxf(m, __shfl_xor_sync(0xffffffffu, m, o));
    float e = fexp2((a - m) * L2E);
    float s = e;
#pragma unroll
    for (int o = 16; o; o >>= 1) s += __shfl_xor_sync(0xffffffffu, s, o);
    g_Aexp[i * 32 + j] = e / s;

    if (i == 0) {
        float p = pi[j];
        float pm = p;
#pragma unroll
        for (int o = 16; o; o >>= 1) pm = fmaxf(pm, __shfl_xor_sync(0xffffffffu, pm, o));
        float pe = fexp2((p - pm) * L2E);
        float ps = pe;
#pragma unroll
        for (int o = 16; o; o >>= 1) ps += __shfl_xor_sync(0xffffffffu, ps, o);
        g_pi02[j] = (p - pm) * L2E - flog2(ps);
    }
    if (i == 1) {
        int k = j;
        float la = log_ab[k * 2 + 0], lb = log_ab[k * 2 + 1];
        float av = expf(la), bv = expf(lb);
        float cg = av * lb - lgammaf(av);
        float sls = 0.f, smm = 0.f;
        for (int d = 0; d < D_; d++) {
            float ls = log_sigma[k * D_ + d];
            float iv = expf(-2.f * ls);
            float mm = mu[k * D_ + d];
            g_muiv[k * D_ + d] = mm * iv;
            g_ivh[k * D_ + d] = -0.5f * iv;
            sls += ls;
            smm += mm * mm * iv;
        }
        g_kc[k] = cg - sls - 0.5f * smm - 0.5f * (float)D_ * logf(6.283185307179586f);
        g_am1[k] = av - 1.f;
        g_bb[k] = bv;
    }
}

// ---------------- K1: weights w[T,32] = exp2(ll2 - c_t), c[T], h copy ----------------
__global__ void __launch_bounds__(128) k1_ll(const float* __restrict__ Y,
                                             const float* __restrict__ dT,
                                             float* __restrict__ hout)
{
    __shared__ float sY[64 * 65];
    __shared__ float sM[32 * 65];
    __shared__ float sH[32 * 65];
    __shared__ float skc[32], sam1[32], sb[32];
    int tid = threadIdx.x;
    size_t t0 = (size_t)blockIdx.x * 64;

    const float4* Y4 = reinterpret_cast<const float4*>(Y);
    float4* h4 = reinterpret_cast<float4*>(hout);
#pragma unroll
    for (int it = 0; it < 8; it++) {
        int f = tid + it * 128;
        float4 v = Y4[t0 * 16 + f];
        h4[t0 * 16 + f] = v;
        int row = f >> 4;
        int col = (f & 15) << 2;
        sY[row * 65 + col + 0] = v.x; sY[row * 65 + col + 1] = v.y;
        sY[row * 65 + col + 2] = v.z; sY[row * 65 + col + 3] = v.w;
    }
#pragma unroll
    for (int it = 0; it < 16; it++) {
        int e = tid + it * 128;
        int k = e >> 6, d = e & 63;
        sM[k * 65 + d] = g_muiv[e];
        sH[k * 65 + d] = g_ivh[e];
    }
    if (tid < 32) { skc[tid] = g_kc[tid]; sam1[tid] = g_am1[tid]; sb[tid] = g_bb[tid]; }
    __syncthreads();

    int kq = tid & 7, tg = tid >> 3;   // 8 k-groups x 16 t-groups
    int k4 = kq * 4, t4 = tg * 4;
    float acc[4][4];
#pragma unroll
    for (int a = 0; a < 4; a++)
#pragma unroll
        for (int b = 0; b < 4; b++) acc[a][b] = 0.f;

#pragma unroll 4
    for (int d = 0; d < 64; d++) {
        float yv[4];
#pragma unroll
        for (int tt = 0; tt < 4; tt++) yv[tt] = sY[(t4 + tt) * 65 + d];
#pragma unroll
        for (int kk = 0; kk < 4; kk++) {
            float mv = sM[(k4 + kk) * 65 + d];
            float hv = sH[(k4 + kk) * 65 + d];
#pragma unroll
            for (int tt = 0; tt < 4; tt++)
                acc[tt][kk] = fmaf(yv[tt], fmaf(hv, yv[tt], mv), acc[tt][kk]);
        }
    }

    float4* wv = reinterpret_cast<float4*>(g_w);
#pragma unroll
    for (int tt = 0; tt < 4; tt++) {
        size_t t = t0 + t4 + tt;
        float dt = dT[t];
        float ldt = logf(dt);
        float llv[4];
        float mx = -3.0e38f;
#pragma unroll
        for (int kk = 0; kk < 4; kk++) {
            int k = k4 + kk;
            float ll = acc[tt][kk] + skc[k] + sam1[k] * ldt - dt * sb[k];
            llv[kk] = ll * L2E;
            mx = fmaxf(mx, llv[kk]);
        }
        mx = fmaxf(mx, __shfl_xor_sync(0xffffffffu, mx, 1));
        mx = fmaxf(mx, __shfl_xor_sync(0xffffffffu, mx, 2));
        mx = fmaxf(mx, __shfl_xor_sync(0xffffffffu, mx, 4));
        float4 o;
        o.x = fexp2(llv[0] - mx); o.y = fexp2(llv[1] - mx);
        o.z = fexp2(llv[2] - mx); o.w = fexp2(llv[3] - mx);
        wv[t * 8 + kq] = o;
        if (kq == 0) g_c[t] = mx;
        if (t == 0) {
#pragma unroll
            for (int kk = 0; kk < 4; kk++) g_ll0[k4 + kk] = llv[kk];
        }
    }
}

// ---------------- K2: chunk scan, linear domain + f32x2 packed FMA ----------------
// Per step: raw = E @ softmax(A); M = raw * diag(w_t); r_i = rowsum; E' = M / r_i;
// O_i += c_t + log2(r_i). Chunk output (log2): log2(E_final) + O_i.
__global__ void __launch_bounds__(64, 14) k2_scan()
{
    __shared__ __align__(16) float sE[2][32 * 36];  // E^T: sE[m][i] = E[i][m]
    __shared__ __align__(16) float sA[32 * 36];     // Aexp row-major [m][j]
    int tid = threadIdx.x;
    int c = blockIdx.x;
    int tc = tid & 7, tr = tid >> 3;
    int j0 = tc * 4, i0 = tr * 4;

#pragma unroll
    for (int it = 0; it < 16; it++) {
        int e = tid + it * 64;
        sA[(e >> 5) * 36 + (e & 31)] = g_Aexp[e];
    }
    int s = 1 + c * CLEN;
    int e_ = min(T_, s + CLEN);
    float O[4] = {0.f, 0.f, 0.f, 0.f};
    U4 w; w.v = *reinterpret_cast<const float4*>(&g_w[(size_t)s * 32 + j0]);
    float cc = g_c[s];
    __syncthreads();

    // init: raw = Aexp rows (pre-weight)
    ull acc[4][2];
#pragma unroll
    for (int ii = 0; ii < 4; ii++) {
        U4 ar; ar.v = *reinterpret_cast<const float4*>(&sA[(i0 + ii) * 36 + j0]);
        acc[ii][0] = ar.u[0]; acc[ii][1] = ar.u[1];
    }

    int p = 0;
    for (int t = s; ; ) {
        // prefetch next-step weights
        U4 wn; float cn = 0.f;
        if (t + 1 < e_) {
            wn.v = *reinterpret_cast<const float4*>(&g_w[(size_t)(t + 1) * 32 + j0]);
            cn = g_c[t + 1];
        } else {
            wn.u[0] = 0ull; wn.u[1] = 0ull;
        }
        // apply column weights
#pragma unroll
        for (int ii = 0; ii < 4; ii++) { MUL2(acc[ii][0], w.u[0]); MUL2(acc[ii][1], w.u[1]); }
        // row sums
        float r[4];
#pragma unroll
        for (int ii = 0; ii < 4; ii++) {
            float2 f = uf(add2(acc[ii][0], acc[ii][1]));
            r[ii] = f.x + f.y;
        }
#pragma unroll
        for (int ii = 0; ii < 4; ii++) {
            r[ii] += __shfl_xor_sync(0xffffffffu, r[ii], 1);
            r[ii] += __shfl_xor_sync(0xffffffffu, r[ii], 2);
            r[ii] += __shfl_xor_sync(0xffffffffu, r[ii], 4);
        }
        // normalize + accumulate offsets
#pragma unroll
        for (int ii = 0; ii < 4; ii++) {
            float rc = frcp(r[ii]);
            O[ii] += cc + flog2(r[ii]);
            ull rcd = dup2(rc);
            MUL2(acc[ii][0], rcd); MUL2(acc[ii][1], rcd);
        }
        // store E^T columns (j-major rows of sE)
        {
            float2 a0 = uf(acc[0][0]), a1 = uf(acc[1][0]), a2 = uf(acc[2][0]), a3 = uf(acc[3][0]);
            float2 b0 = uf(acc[0][1]), b1 = uf(acc[1][1]), b2 = uf(acc[2][1]), b3 = uf(acc[3][1]);
            *reinterpret_cast<float4*>(&sE[p][(j0 + 0) * 36 + i0]) = make_float4(a0.x, a1.x, a2.x, a3.x);
            *reinterpret_cast<float4*>(&sE[p][(j0 + 1) * 36 + i0]) = make_float4(a0.y, a1.y, a2.y, a3.y);
            *reinterpret_cast<float4*>(&sE[p][(j0 + 2) * 36 + i0]) = make_float4(b0.x, b1.x, b2.x, b3.x);
            *reinterpret_cast<float4*>(&sE[p][(j0 + 3) * 36 + i0]) = make_float4(b0.y, b1.y, b2.y, b3.y);
        }
        __syncthreads();
        t++;
        if (t >= e_) break;
        w = wn; cc = cn;
        // raw = E @ Aexp via packed f32x2 FMA
#pragma unroll
        for (int ii = 0; ii < 4; ii++) { acc[ii][0] = 0ull; acc[ii][1] = 0ull; }
#pragma unroll
        for (int m = 0; m < 32; m++) {
            float4 a = *reinterpret_cast<const float4*>(&sE[p][m * 36 + i0]);
            U4 b; b.v = *reinterpret_cast<const float4*>(&sA[m * 36 + j0]);
            ull d0 = dup2(a.x), d1 = dup2(a.y), d2 = dup2(a.z), d3 = dup2(a.w);
            FMA2(acc[0][0], d0, b.u[0]); FMA2(acc[0][1], d0, b.u[1]);
            FMA2(acc[1][0], d1, b.u[0]); FMA2(acc[1][1], d1, b.u[1]);
            FMA2(acc[2][0], d2, b.u[0]); FMA2(acc[2][1], d2, b.u[1]);
            FMA2(acc[3][0], d3, b.u[0]); FMA2(acc[3][1], d3, b.u[1]);
        }
        p ^= 1;
    }
    // emit chunk matrix (log2 domain)
#pragma unroll
    for (int ii = 0; ii < 4; ii++) {
        float4 o;
        o.x = flog2(sE[p][(j0 + 0) * 36 + i0 + ii]) + O[ii];
        o.y = flog2(sE[p][(j0 + 1) * 36 + i0 + ii]) + O[ii];
        o.z = flog2(sE[p][(j0 + 2) * 36 + i0 + ii]) + O[ii];
        o.w = flog2(sE[p][(j0 + 3) * 36 + i0 + ii]) + O[ii];
        *reinterpret_cast<float4*>(&g_M[0][(size_t)c * 1024 + (i0 + ii) * 32 + j0]) = o;
    }
}

// ---------------- K3: fused multi-level LSE-matmul reduce (G mats per block) ----------------
__global__ void __launch_bounds__(1024, 1) k3f(int srcSel, int G, int nmat)
{
    const float* __restrict__ src = g_M[srcSel];
    float* __restrict__ dst = g_M[srcSel ^ 1];
    __shared__ float cur[32 * 33];
    __shared__ float nb[32 * 33];
    int tid = threadIdx.x;
    int i = tid >> 5, j = tid & 31;
    size_t base = (size_t)blockIdx.x * G * 1024;
    int cnt = min(G, nmat - blockIdx.x * G);
    cur[i * 33 + j] = src[base + i * 32 + j];
    __syncthreads();
    for (int g = 1; g < cnt; g++) {
        nb[i * 33 + j] = src[base + (size_t)g * 1024 + i * 32 + j];
        __syncthreads();
        float v[32];
        float vm = -3.0e38f;
#pragma unroll
        for (int m = 0; m < 32; m++) {
            v[m] = cur[i * 33 + m] + nb[m * 33 + j];
            vm = fmaxf(vm, v[m]);
        }
        float ssum = 0.f;
#pragma unroll
        for (int m = 0; m < 32; m++) ssum += fexp2(v[m] - vm);
        float outv = vm + flog2(ssum);
        __syncthreads();
        cur[i * 33 + j] = outv;
        // next iteration's nb store + sync covers visibility of cur
        __syncthreads();
    }
    dst[(size_t)blockIdx.x * 1024 + i * 32 + j] = cur[i * 33 + j];
}

// ---------------- K4: contract alpha0 with final matrix -> loss ----------------
__global__ void k4_final(float* __restrict__ out, int outIdx, int sel)
{
    __shared__ float red[32];
    __shared__ float bval;
    int tid = threadIdx.x;
    int i = tid >> 5, j = tid & 31;
    float v = g_pi02[i] + g_ll0[i] + g_M[sel][i * 32 + j];
    float m = v;
#pragma unroll
    for (int o = 16; o; o >>= 1) m = fmaxf(m, __shfl_xor_sync(0xffffffffu, m, o));
    if (j == 0) red[i] = m;
    __syncthreads();
    if (tid < 32) {
        float t = red[tid];
#pragma unroll
        for (int o = 16; o; o >>= 1) t = fmaxf(t, __shfl_xor_sync(0xffffffffu, t, o));
        if (tid == 0) bval = t;
    }
    __syncthreads();
    float bmax = bval;
    float e = fexp2(v - bmax);
#pragma unroll
    for (int o = 16; o; o >>= 1) e += __shfl_xor_sync(0xffffffffu, e, o);
    __syncthreads();
    if (j == 0) red[i] = e;
    __syncthreads();
    if (tid < 32) {
        float t = red[tid];
#pragma unroll
        for (int o = 16; o; o >>= 1) t += __shfl_xor_sync(0xffffffffu, t, o);
        if (tid == 0) out[outIdx] = -((bmax + flog2(t)) * LN2);
    }
}

// ---------------- launch ----------------
extern "C" void kernel_launch(void* const* d_in, const int* in_sizes, int n_in,
                              void* d_out, int out_size)
{
    const float* Y = (const float*)d_in[0];
    const float* dT = (const float*)d_in[1];
    const float* A = (const float*)d_in[2];
    const float* log_ab = (const float*)d_in[3];
    const float* mu = (const float*)d_in[4];
    const float* log_sigma = (const float*)d_in[5];
    const float* pi = (const float*)d_in[6];
    float* out = (float*)d_out;

    k0_setup<<<1, 1024>>>(A, log_ab, mu, log_sigma, pi);
    k1_ll<<<T_ / 64, 128>>>(Y, dT, out);
    k2_scan<<<CHUNKS, 64>>>();
    int P = CHUNKS, sel = 0;
    while (P > 1) {
        int G = (P > 16) ? 16 : P;
        int nb = (P + G - 1) / G;
        k3f<<<nb, 1024>>>(sel, G, P);
        sel ^= 1;
        P = nb;
    }
    k4_final<<<1, 1024>>>(out, out_size - 1, sel);
}